// round 2
// baseline (speedup 1.0000x reference)
#include <cuda_runtime.h>
#include <math_constants.h>

#define TT 4096
#define NB 8
#define NEGF (-CUDART_INF_F)

__device__ __forceinline__ float pen(float yv, float idx, float eps) {
    return fmaxf(0.0f, fabsf(yv - idx) - eps);
}

__global__ void __launch_bounds__(1024, 1)
custom_loss_1cta(const float* __restrict__ X,   // (8, 1, 4096)
                 const float* __restrict__ Y,   // (8, 2)
                 const unsigned* __restrict__ epsb,
                 float* __restrict__ out)       // scalar
{
    const int tid  = threadIdx.x;
    const int w    = tid >> 5;        // warp 0..31
    const int lane = tid & 31;
    const int b    = w >> 2;          // batch 0..7 (4 warps per batch)
    const int c    = w & 3;           // chunk 0..3 within batch

    // eps may arrive as int32 or float32 bits; int 5 reinterpreted as float is
    // a denormal << 1e-6, so this test is unambiguous.
    const unsigned eb = *epsb;
    const float    ef = __uint_as_float(eb);
    const float eps = (ef >= 1e-6f && ef <= 1e9f) ? ef : (float)(int)eb;

    const float y0 = Y[2 * b + 0];
    const float y1 = Y[2 * b + 1];

    const int sl = (c << 10) + (lane << 5);      // local start index, 32 elems/lane
    const float* xb = X + b * TT;

    // 32 contiguous values via 8x float4 (aligned, in-bounds)
    float xa[32];
#pragma unroll
    for (int q = 0; q < 8; q++) {
        float4 v = reinterpret_cast<const float4*>(xb + sl)[q];
        xa[4*q+0] = v.x; xa[4*q+1] = v.y; xa[4*q+2] = v.z; xa[4*q+3] = v.w;
    }
    // tail x[sl+32 .. sl+36] for the +5 shift (guarded to stay inside batch)
    float xt[5];
#pragma unroll
    for (int r = 0; r < 5; r++) {
        int ix = sl + 32 + r;
        xt[r] = (ix < TT) ? __ldg(xb + ix) : 0.0f;
    }

    // descending scan over this lane's segment:
    //   a'[k] = x[k] + .5*pen(y0,k)    masked to k >= 5
    //   b'[k] = x[k+5] + .5*pen(y1,k+5)  valid while k+5 < TT
    //   P = max_{i<=k in seg} a'[i] + b'[k];  A = max a';  Bm = max b'
    float P = NEGF, A = NEGF, suffB = NEGF;
#pragma unroll
    for (int t = 31; t >= 0; t--) {
        const int   k  = sl + t;
        const int   j  = k + 5;
        const float xj = (t <= 26) ? xa[t + 5] : xt[t - 27];
        const float bv = (j < TT) ? (xj + 0.5f * pen(y1, (float)j, eps)) : NEGF;
        suffB = fmaxf(suffB, bv);
        const float av = (k >= 5) ? (xa[t] + 0.5f * pen(y0, (float)k, eps)) : NEGF;
        A = fmaxf(A, av);
        P = fmaxf(P, av + suffB);
    }
    float Bm = suffB;

    // ordered warp combine (lane l holds segment l; ascending order): 5 levels
#pragma unroll
    for (int off = 1; off < 32; off <<= 1) {
        float Pr = __shfl_down_sync(0xffffffffu, P,  off);
        float Ar = __shfl_down_sync(0xffffffffu, A,  off);
        float Br = __shfl_down_sync(0xffffffffu, Bm, off);
        if (lane + off < 32) {
            P  = fmaxf(fmaxf(P, Pr), A + Br);
            A  = fmaxf(A, Ar);
            Bm = fmaxf(Bm, Br);
        }
    }

    __shared__ float sP[32], sA[32], sB[32];
    __shared__ float sOut[NB];
    if (lane == 0) { sP[w] = P; sA[w] = A; sB[w] = Bm; }
    __syncthreads();

    // threads 0..7: combine the 4 chunk-triples of batch tid (in ascending order)
    if (tid < NB) {
        const int base = tid << 2;
        float p = sP[base], a = sA[base];
#pragma unroll
        for (int q = 1; q < 4; q++) {
            p = fmaxf(fmaxf(p, sP[base + q]), a + sB[base + q]);
            a = fmaxf(a, sA[base + q]);
        }
        const float* xq = X + tid * TT;
        const float yy0 = Y[2 * tid + 0];
        const float yy1 = Y[2 * tid + 1];
        // init term is UNMASKED: a[1] + b[1+MIN_SIZE] = a[1] + b[6]
        const float init = (xq[1] + 0.5f * pen(yy0, 1.0f, eps))
                         + (xq[6] + 0.5f * pen(yy1, 6.0f, eps));
        sOut[tid] = fmaxf(p, init);
    }
    __syncthreads();

    if (tid == 0) {
        float ssum = 0.0f;
#pragma unroll
        for (int q = 0; q < NB; q++) ssum += sOut[q];   // fixed order -> deterministic
        out[0] = ssum * (1.0f / NB);
    }
}

extern "C" void kernel_launch(void* const* d_in, const int* in_sizes, int n_in,
                              void* d_out, int out_size) {
    const float*    w_phi = (const float*)d_in[0];
    const float*    y     = (const float*)d_in[1];
    const unsigned* epsb  = (const unsigned*)d_in[2];
    float*          out   = (float*)d_out;
    custom_loss_1cta<<<1, 1024>>>(w_phi, y, epsb, out);
}

// round 3
// speedup vs baseline: 2.0000x; 2.0000x over previous
#include <cuda_runtime.h>
#include <math_constants.h>

#define TT 4096
#define NB 8
#define NEGF (-CUDART_INF_F)

// fused accumulator: bits[56:63] = arrival count, bits[0:55] = biased fixed-point sum
__device__ unsigned long long g_sum = 0ULL;

#define FP_SCALE 16777216.0f          /* 2^24 */
#define FP_BIAS  (1LL << 45)
#define CNT_ONE  (1ULL << 56)
#define SUM_MASK ((1ULL << 56) - 1ULL)

__device__ __forceinline__ float pen(float yv, float idx, float eps) {
    return fmaxf(0.0f, fabsf(yv - idx) - eps);
}

__global__ void __launch_bounds__(256, 1)
custom_loss_kernel(const float* __restrict__ X,   // (8, 1, 4096)
                   const float* __restrict__ Y,   // (8, 2)
                   const unsigned* __restrict__ epsb,
                   float* __restrict__ out)       // scalar
{
    const int b    = blockIdx.x;
    const int tid  = threadIdx.x;
    const int w    = tid >> 5;
    const int lane = tid & 31;

    const float* xb = X + b * TT;
    const float y0 = Y[2 * b + 0];
    const float y1 = Y[2 * b + 1];

    // eps arrives as int32 or float32 bits; int 5 as float bits is a denormal.
    const unsigned eb = *epsb;
    const float    ef = __uint_as_float(eb);
    const float eps = (ef >= 1e-6f && ef <= 1e9f) ? ef : (float)(int)eb;

    const int sl = (w << 9) + (lane << 4);       // 16 contiguous elems per lane

    // main segment: 4x float4 (aligned, in-bounds)
    float xa[16];
#pragma unroll
    for (int q = 0; q < 4; q++) {
        float4 v = reinterpret_cast<const float4*>(xb + sl)[q];
        xa[4*q+0] = v.x; xa[4*q+1] = v.y; xa[4*q+2] = v.z; xa[4*q+3] = v.w;
    }
    // tail x[sl+16 .. sl+20] for the +5 shift; only the sl=4080 lane skips
    // (its tail values are provably unused: j >= TT there).
    float xt[5];
    if (sl < TT - 20) {
        float4 v = *reinterpret_cast<const float4*>(xb + sl + 16);
        xt[0] = v.x; xt[1] = v.y; xt[2] = v.z; xt[3] = v.w;
        xt[4] = xb[sl + 20];
    } else {
#pragma unroll
        for (int r = 0; r < 5; r++) xt[r] = 0.0f;
    }

    // descending scan:
    //   a'[k] = x[k] + .5*pen(y0,k)      masked to k >= 5
    //   b'[k] = x[k+5] + .5*pen(y1,k+5)  valid while k+5 < TT
    //   P = max_{i<=k in seg} a'[i]+b'[k];  A = max a';  Bm = max b'
    float P = NEGF, A = NEGF, suffB = NEGF;
#pragma unroll
    for (int t = 15; t >= 0; t--) {
        const int   k  = sl + t;
        const int   j  = k + 5;
        const float xj = (t <= 10) ? xa[t + 5] : xt[t - 11];
        const float bv = (j < TT) ? (xj + 0.5f * pen(y1, (float)j, eps)) : NEGF;
        suffB = fmaxf(suffB, bv);
        const float av = (k >= 5) ? (xa[t] + 0.5f * pen(y0, (float)k, eps)) : NEGF;
        A = fmaxf(A, av);
        P = fmaxf(P, av + suffB);
    }
    float Bm = suffB;

    // fold the UNMASKED init term a[1] + b[6] into the sl==0 lane's P
    if (sl == 0) {
        const float init = (xa[1] + 0.5f * pen(y0, 1.0f, eps))
                         + (xa[6] + 0.5f * pen(y1, 6.0f, eps));
        P = fmaxf(P, init);
    }

    // ordered warp combine (lane l owns segment l, ascending)
#pragma unroll
    for (int off = 1; off < 32; off <<= 1) {
        float Pr = __shfl_down_sync(0xffffffffu, P,  off);
        float Ar = __shfl_down_sync(0xffffffffu, A,  off);
        float Br = __shfl_down_sync(0xffffffffu, Bm, off);
        if (lane + off < 32) {
            P  = fmaxf(fmaxf(P, Pr), A + Br);
            A  = fmaxf(A, Ar);
            Bm = fmaxf(Bm, Br);
        }
    }

    __shared__ float sP[8], sA[8], sB[8];
    if (lane == 0) { sP[w] = P; sA[w] = A; sB[w] = Bm; }
    __syncthreads();

    if (tid == 0) {
        float p = sP[0], a = sA[0];
#pragma unroll
        for (int q = 1; q < 8; q++) {
            p = fmaxf(fmaxf(p, sP[q]), a + sB[q]);
            a = fmaxf(a, sA[q]);
        }
        // fixed-point encode; one fused atomic carries both count and sum.
        const long long ll = llrintf(p * FP_SCALE) + FP_BIAS;
        const unsigned long long v   = CNT_ONE + (unsigned long long)ll;
        const unsigned long long old = atomicAdd(&g_sum, v);
        if ((old >> 56) == NB - 1) {                 // this CTA completed the sum
            const long long tot =
                (long long)((old + v) & SUM_MASK) - (long long)NB * FP_BIAS;
            out[0] = (float)((double)tot * (1.0 / (FP_SCALE * (double)NB)));
            g_sum = 0ULL;                            // re-arm for next replay
        }
    }
}

extern "C" void kernel_launch(void* const* d_in, const int* in_sizes, int n_in,
                              void* d_out, int out_size) {
    const float*    w_phi = (const float*)d_in[0];
    const float*    y     = (const float*)d_in[1];
    const unsigned* epsb  = (const unsigned*)d_in[2];
    float*          out   = (float*)d_out;
    custom_loss_kernel<<<NB, 256>>>(w_phi, y, epsb, out);
}